// round 14
// baseline (speedup 1.0000x reference)
#include <cuda_runtime.h>
#include <math.h>

#define BB 8
#define AA 49104
#define MM 50
#define KK 80
#define TPB 256
#define NBLKX_SWP 148
#define NBLKX_SCR 96
#define SCR_APB 512                       // anchors per screen block
#define NBLKX (NBLKX_SWP + NBLKX_SCR)     // 244
#define NBLKS (NBLKX * BB)                // 1952

// zero-initialized at module load; finalizer re-zeros after each consume,
// so every graph replay starts clean.
__device__ float g_cls_raw[BB];
__device__ float g_reg_raw[BB];
__device__ int   g_numpos[BB];
__device__ unsigned int g_done;

__device__ __forceinline__ float smooth_l1(float d) {
    const float BETA = 1.0f / 9.0f;
    float ad = fabsf(d);
    return (ad <= BETA) ? (4.5f * ad * ad) : (ad - 0.5f * BETA);
}

// focal bulk term for one float4 of probabilities: sum p^2 * log2(1-p)
__device__ __forceinline__ float focal4(float4 p4) {
    return p4.x * p4.x * __log2f(1.0f - p4.x)
         + p4.y * p4.y * __log2f(1.0f - p4.y)
         + p4.z * p4.z * __log2f(1.0f - p4.z)
         + p4.w * p4.w * __log2f(1.0f - p4.w);
}

__device__ __forceinline__ void finalize_if_last(float* out) {
    __threadfence();
    unsigned int prev = atomicAdd(&g_done, 1u);
    if (prev == NBLKS - 1) {
        float cm = 0.0f, rm = 0.0f;
        #pragma unroll
        for (int bb = 0; bb < BB; ++bb) {
            float np = fmaxf((float)g_numpos[bb], 1.0f);
            cm += (-0.75f * 0.69314718055994531f) * g_cls_raw[bb] / np;
            rm += g_reg_raw[bb] / (4.0f * np);
            g_cls_raw[bb] = 0.0f;
            g_reg_raw[bb] = 0.0f;
            g_numpos[bb] = 0;
        }
        cm *= (1.0f / (float)BB);
        rm *= (1.0f / (float)BB);
        out[0] = cm;
        out[1] = rm;
        out[2] = cm + rm;
        g_done = 0u;
    }
}

__global__ __launch_bounds__(TPB, 6) void retina_hetero_kernel(
    const float* __restrict__ logits,   // (B,A,K)
    const float* __restrict__ regp,     // (B,A,4)
    const float* __restrict__ anchors,  // (A,4)
    const float* __restrict__ boxes,    // (B,M,4)
    const int*   __restrict__ cls,      // (B,M)
    float* __restrict__ out)
{
    const int b = blockIdx.y;
    const int tid = threadIdx.x;
    const int lane = tid & 31;
    const int wrp = tid >> 5;

    __shared__ float wsum[8], wsum2[8];

    float s = 0.0f;      // classification partial (units of p^2*log2(...))
    float rsum = 0.0f;   // regression partial
    int   myblk_pos = 0; // per-block positive count (only tid-summed later)

    if (blockIdx.x < NBLKX_SWP) {
        // ================= SWEEP ROLE: pure unconditional stream =================
        const float4* __restrict__ L4 = (const float4*)(logits + (size_t)b * AA * KK);
        const unsigned N4 = AA * (KK / 4);              // 982080
        const unsigned stride = NBLKX_SWP * TPB;        // 37888
        unsigned i = blockIdx.x * TPB + tid;

        float s0 = 0.0f, s1 = 0.0f, s2 = 0.0f, s3 = 0.0f;
        for (; i + 3 * stride < N4; i += 4 * stride) {
            float4 p0 = L4[i];
            float4 p1 = L4[i + stride];
            float4 p2 = L4[i + 2 * stride];
            float4 p3 = L4[i + 3 * stride];
            s0 += focal4(p0);
            s1 += focal4(p1);
            s2 += focal4(p2);
            s3 += focal4(p3);
        }
        for (; i < N4; i += stride) s0 += focal4(L4[i]);
        s = (s0 + s1) + (s2 + s3);
    } else {
        // ================= SCREEN ROLE: assign + corrections =================
        const int xs = blockIdx.x - NBLKX_SWP;       // 0..95
        const int aStart = xs * SCR_APB;

        __shared__ float4 sbox[MM];
        __shared__ float4 saux[MM];   // (2/7)sb, (1/3)sb, sb, cls-bits
        __shared__ int    siglist[SCR_APB];
        __shared__ int    sigcnt, snv;

        if (tid == 0) { sigcnt = 0; snv = MM; }
        __syncthreads();
        if (tid < MM) {
            float4 bx = ((const float4*)boxes)[b * MM + tid];
            float sb = (bx.z - bx.x) * (bx.w - bx.y);
            sbox[tid] = bx;
            float4 au;
            au.x = sb * (2.0f / 7.0f);   // 0.4/(1+0.4) * sb
            au.y = sb * (1.0f / 3.0f);   // 0.5/(1+0.5) * sb
            au.z = sb;
            au.w = __int_as_float(cls[b * MM + tid]);
            saux[tid] = au;
            if (bx.x == -1.0f) atomicMin(&snv, tid);   // valid-first padding
        }
        __syncthreads();
        const int nv = snv;   // uniform -> no divergence

        int npos = 0;
        #pragma unroll
        for (int pass = 0; pass < SCR_APB / TPB; ++pass) {
            const int a = aStart + tid + pass * TPB;
            if (a >= AA) continue;
            float4 an = ((const float4*)anchors)[a];
            const float ax1 = an.x, ay1 = an.y, ax2 = an.z, ay2 = an.w;
            const float aw = ax2 - ax1, ah = ay2 - ay1;
            const float sa = aw * ah;

            // screen: iou >= t <=> inter >= t/(1+t)*(sa+sb), FFMA-fused
            float m4 = -1e30f, m5 = -1e30f;
            #pragma unroll 5
            for (int j = 0; j < nv; ++j) {
                float4 bx = sbox[j];
                float4 au = saux[j];
                float iw = fmaxf(fminf(ax2, bx.z) - fmaxf(ax1, bx.x), 0.0f);
                float ih = fminf(ay2, bx.w) - fmaxf(ay1, bx.y);
                m4 = fmaxf(m4, __fmaf_rn(iw, ih, -au.x));
                m5 = fmaxf(m5, __fmaf_rn(iw, ih, -au.y));
            }
            const bool pos = (m5 >= sa * (1.0f / 3.0f));   // iou_max >= 0.5
            const bool neg = (m4 <  sa * (2.0f / 7.0f));   // iou_max < 0.4

            if (!pos && !neg) {
                // ignore anchor: enqueue its row for subtraction
                siglist[atomicAdd(&sigcnt, 1)] = a;
            }

            if (pos) {
                npos++;
                // division-free argmax of iou (first-max by strict '>')
                float bi = -1.0f, bu = 1.0f;
                int bj = 0;
                for (int j = 0; j < nv; ++j) {
                    float4 bx = sbox[j];
                    float iw = fmaxf(fminf(ax2, bx.z) - fmaxf(ax1, bx.x), 0.0f);
                    float ih = fmaxf(fminf(ay2, bx.w) - fmaxf(ay1, bx.y), 0.0f);
                    float inter = iw * ih;
                    float ua = fmaxf(sa + saux[j].z - inter, 1e-8f);
                    if (inter * bu > bi * ua) { bi = inter; bu = ua; bj = j; }
                }

                // focal correction on the positive class
                int c = __float_as_int(saux[bj].w) - 1;
                float praw = __ldg(logits + ((size_t)b * AA + a) * KK + c);
                float p = fminf(fmaxf(praw, 1e-4f), 1.0f - 1e-4f);
                float q = 1.0f - p;
                s += (1.0f / 3.0f) * q * q * __log2f(p) - p * p * __log2f(q);

                // regression smooth-L1
                float4 gb = sbox[bj];
                float acx = ax1 + 0.5f * aw;
                float acy = ay1 + 0.5f * ah;
                float gw0 = gb.z - gb.x, gh0 = gb.w - gb.y;
                float gcx = gb.x + 0.5f * gw0;
                float gcy = gb.y + 0.5f * gh0;
                float gw = fmaxf(gw0, 1.0f), gh = fmaxf(gh0, 1.0f);
                float4 rp = ((const float4*)regp)[b * AA + a];
                float t0 = ((gcx - acx) / aw) * 10.0f;
                float t1 = ((gcy - acy) / ah) * 10.0f;
                float t2 = logf(gw / aw) * 5.0f;
                float t3 = logf(gh / ah) * 5.0f;
                rsum += smooth_l1(t0 - rp.x) + smooth_l1(t1 - rp.y)
                      + smooth_l1(t2 - rp.z) + smooth_l1(t3 - rp.w);
            }
        }
        myblk_pos = npos;
        __syncthreads();
        const int nign = sigcnt;

        // ---- warp-cooperative ignore-row subtraction (one warp per row) ----
        for (int i = wrp; i < nign; i += TPB / 32) {
            const int a = siglist[i];
            const float4* row4 = (const float4*)(logits + ((size_t)b * AA + a) * KK);
            float t = (lane < KK / 4) ? focal4(row4[lane]) : 0.0f;
            #pragma unroll
            for (int o = 16; o > 0; o >>= 1)
                t += __shfl_down_sync(0xffffffffu, t, o);
            if (lane == 0) s -= t;
        }
    }

    // ---------- block reduction, one atomic each ----------
    #pragma unroll
    for (int o = 16; o > 0; o >>= 1) {
        s    += __shfl_down_sync(0xffffffffu, s, o);
        rsum += __shfl_down_sync(0xffffffffu, rsum, o);
        myblk_pos += __shfl_down_sync(0xffffffffu, myblk_pos, o);
    }
    __shared__ int psum[8];
    if (lane == 0) { wsum[wrp] = s; wsum2[wrp] = rsum; psum[wrp] = myblk_pos; }
    __syncthreads();

    if (tid == 0) {
        float t = 0.0f, t2 = 0.0f;
        int np = 0;
        #pragma unroll
        for (int i = 0; i < 8; ++i) { t += wsum[i]; t2 += wsum2[i]; np += psum[i]; }
        if (t != 0.0f)  atomicAdd(&g_cls_raw[b], t);
        if (t2 != 0.0f) atomicAdd(&g_reg_raw[b], t2);
        if (np)         atomicAdd(&g_numpos[b], np);
        finalize_if_last(out);
    }
}

extern "C" void kernel_launch(void* const* d_in, const int* in_sizes, int n_in,
                              void* d_out, int out_size) {
    const float* logits  = (const float*)d_in[0];
    const float* regp    = (const float*)d_in[1];
    const float* anchors = (const float*)d_in[2];
    const float* boxes   = (const float*)d_in[3];
    const int*   cls     = (const int*)d_in[4];
    float* out = (float*)d_out;

    dim3 grid(NBLKX, BB);
    retina_hetero_kernel<<<grid, TPB>>>(logits, regp, anchors, boxes, cls, out);
}

// round 16
// speedup vs baseline: 1.0144x; 1.0144x over previous
#include <cuda_runtime.h>
#include <math.h>

#define BB 8
#define AA 49104
#define MM 50
#define KK 80
#define TPB 256
#define NBLKX_SWP 148
#define NBLKX_SCR 96
#define SCR_APB 512                       // anchors per screen block
#define NBLKX (NBLKX_SWP + NBLKX_SCR)     // 244
#define NBLKS (NBLKX * BB)                // 1952
#define N4    (AA * (KK / 4))             // 982080 float4s per image
#define CHUNK 6656                        // float4s per sweep block (148*6656 >= N4)

// zero-initialized at module load; finalizer re-zeros after each consume,
// so every graph replay starts clean.
__device__ float g_cls_raw[BB];
__device__ float g_reg_raw[BB];
__device__ int   g_numpos[BB];
__device__ unsigned int g_done;

__device__ __forceinline__ float smooth_l1(float d) {
    const float BETA = 1.0f / 9.0f;
    float ad = fabsf(d);
    return (ad <= BETA) ? (4.5f * ad * ad) : (ad - 0.5f * BETA);
}

// focal bulk term for one float4 of probabilities: sum p^2 * log2(1-p)
__device__ __forceinline__ float focal4(float4 p4) {
    return p4.x * p4.x * __log2f(1.0f - p4.x)
         + p4.y * p4.y * __log2f(1.0f - p4.y)
         + p4.z * p4.z * __log2f(1.0f - p4.z)
         + p4.w * p4.w * __log2f(1.0f - p4.w);
}

__device__ __forceinline__ void finalize_if_last(float* out) {
    __threadfence();
    unsigned int prev = atomicAdd(&g_done, 1u);
    if (prev == NBLKS - 1) {
        float cm = 0.0f, rm = 0.0f;
        #pragma unroll
        for (int bb = 0; bb < BB; ++bb) {
            float np = fmaxf((float)g_numpos[bb], 1.0f);
            cm += (-0.75f * 0.69314718055994531f) * g_cls_raw[bb] / np;
            rm += g_reg_raw[bb] / (4.0f * np);
            g_cls_raw[bb] = 0.0f;
            g_reg_raw[bb] = 0.0f;
            g_numpos[bb] = 0;
        }
        cm *= (1.0f / (float)BB);
        rm *= (1.0f / (float)BB);
        out[0] = cm;
        out[1] = rm;
        out[2] = cm + rm;
        g_done = 0u;
    }
}

__global__ __launch_bounds__(TPB, 6) void retina_hetero_kernel(
    const float* __restrict__ logits,   // (B,A,K)
    const float* __restrict__ regp,     // (B,A,4)
    const float* __restrict__ anchors,  // (A,4)
    const float* __restrict__ boxes,    // (B,M,4)
    const int*   __restrict__ cls,      // (B,M)
    float* __restrict__ out)
{
    const int b = blockIdx.y;
    const int tid = threadIdx.x;
    const int lane = tid & 31;
    const int wrp = tid >> 5;

    __shared__ float wsum[8], wsum2[8];

    float s = 0.0f;      // classification partial (units of p^2*log2(...))
    float rsum = 0.0f;   // regression partial
    int   myblk_pos = 0;

    if (blockIdx.x < NBLKX_SWP) {
        // ======== SWEEP ROLE: contiguous 104KB chunk, 8 load chains, evict-first ========
        const float4* __restrict__ L4 = (const float4*)(logits + (size_t)b * AA * KK);
        const unsigned beg = blockIdx.x * CHUNK;
        const unsigned end = min(beg + CHUNK, (unsigned)N4);

        float s0 = 0.0f, s1 = 0.0f, s2 = 0.0f, s3 = 0.0f;
        unsigned j = beg + tid;
        for (; j + 7u * TPB < end; j += 8u * TPB) {
            // 8 independent LDG.128 (streaming, no L2 retention)
            float4 p0 = __ldcs(&L4[j]);
            float4 p1 = __ldcs(&L4[j + 1u * TPB]);
            float4 p2 = __ldcs(&L4[j + 2u * TPB]);
            float4 p3 = __ldcs(&L4[j + 3u * TPB]);
            float4 p4 = __ldcs(&L4[j + 4u * TPB]);
            float4 p5 = __ldcs(&L4[j + 5u * TPB]);
            float4 p6 = __ldcs(&L4[j + 6u * TPB]);
            float4 p7 = __ldcs(&L4[j + 7u * TPB]);
            s0 += focal4(p0);
            s1 += focal4(p1);
            s2 += focal4(p2);
            s3 += focal4(p3);
            s0 += focal4(p4);
            s1 += focal4(p5);
            s2 += focal4(p6);
            s3 += focal4(p7);
        }
        for (; j < end; j += TPB)
            s0 += focal4(__ldcs(&L4[j]));
        s = (s0 + s1) + (s2 + s3);
    } else {
        // ================= SCREEN ROLE: assign + corrections =================
        const int xs = blockIdx.x - NBLKX_SWP;       // 0..95
        const int aStart = xs * SCR_APB;

        __shared__ float4 sbox[MM];
        __shared__ float4 saux[MM];   // (2/7)sb, (1/3)sb, sb, cls-bits
        __shared__ int    siglist[SCR_APB];
        __shared__ int    sigcnt, snv;

        if (tid == 0) { sigcnt = 0; snv = MM; }
        __syncthreads();
        if (tid < MM) {
            float4 bx = ((const float4*)boxes)[b * MM + tid];
            float sb = (bx.z - bx.x) * (bx.w - bx.y);
            sbox[tid] = bx;
            float4 au;
            au.x = sb * (2.0f / 7.0f);   // 0.4/(1+0.4) * sb
            au.y = sb * (1.0f / 3.0f);   // 0.5/(1+0.5) * sb
            au.z = sb;
            au.w = __int_as_float(cls[b * MM + tid]);
            saux[tid] = au;
            if (bx.x == -1.0f) atomicMin(&snv, tid);   // valid-first padding
        }
        __syncthreads();
        const int nv = snv;   // uniform -> no divergence

        int npos = 0;
        #pragma unroll
        for (int pass = 0; pass < SCR_APB / TPB; ++pass) {
            const int a = aStart + tid + pass * TPB;
            if (a >= AA) continue;
            float4 an = ((const float4*)anchors)[a];
            const float ax1 = an.x, ay1 = an.y, ax2 = an.z, ay2 = an.w;
            const float aw = ax2 - ax1, ah = ay2 - ay1;
            const float sa = aw * ah;

            // screen: iou >= t <=> inter >= t/(1+t)*(sa+sb), FFMA-fused
            float m4 = -1e30f, m5 = -1e30f;
            #pragma unroll 5
            for (int j = 0; j < nv; ++j) {
                float4 bx = sbox[j];
                float4 au = saux[j];
                float iw = fmaxf(fminf(ax2, bx.z) - fmaxf(ax1, bx.x), 0.0f);
                float ih = fminf(ay2, bx.w) - fmaxf(ay1, bx.y);
                m4 = fmaxf(m4, __fmaf_rn(iw, ih, -au.x));
                m5 = fmaxf(m5, __fmaf_rn(iw, ih, -au.y));
            }
            const bool pos = (m5 >= sa * (1.0f / 3.0f));   // iou_max >= 0.5
            const bool neg = (m4 <  sa * (2.0f / 7.0f));   // iou_max < 0.4

            if (!pos && !neg) siglist[atomicAdd(&sigcnt, 1)] = a;

            if (pos) {
                npos++;
                // division-free argmax of iou (first-max by strict '>')
                float bi = -1.0f, bu = 1.0f;
                int bj = 0;
                for (int j = 0; j < nv; ++j) {
                    float4 bx = sbox[j];
                    float iw = fmaxf(fminf(ax2, bx.z) - fmaxf(ax1, bx.x), 0.0f);
                    float ih = fmaxf(fminf(ay2, bx.w) - fmaxf(ay1, bx.y), 0.0f);
                    float inter = iw * ih;
                    float ua = fmaxf(sa + saux[j].z - inter, 1e-8f);
                    if (inter * bu > bi * ua) { bi = inter; bu = ua; bj = j; }
                }

                // focal correction on the positive class
                int c = __float_as_int(saux[bj].w) - 1;
                float praw = __ldg(logits + ((size_t)b * AA + a) * KK + c);
                float p = fminf(fmaxf(praw, 1e-4f), 1.0f - 1e-4f);
                float q = 1.0f - p;
                s += (1.0f / 3.0f) * q * q * __log2f(p) - p * p * __log2f(q);

                // regression smooth-L1
                float4 gb = sbox[bj];
                float acx = ax1 + 0.5f * aw;
                float acy = ay1 + 0.5f * ah;
                float gw0 = gb.z - gb.x, gh0 = gb.w - gb.y;
                float gcx = gb.x + 0.5f * gw0;
                float gcy = gb.y + 0.5f * gh0;
                float gw = fmaxf(gw0, 1.0f), gh = fmaxf(gh0, 1.0f);
                float4 rp = ((const float4*)regp)[b * AA + a];
                float t0 = ((gcx - acx) / aw) * 10.0f;
                float t1 = ((gcy - acy) / ah) * 10.0f;
                float t2 = logf(gw / aw) * 5.0f;
                float t3 = logf(gh / ah) * 5.0f;
                rsum += smooth_l1(t0 - rp.x) + smooth_l1(t1 - rp.y)
                      + smooth_l1(t2 - rp.z) + smooth_l1(t3 - rp.w);
            }
        }
        myblk_pos = npos;
        __syncthreads();
        const int nign = sigcnt;

        // ---- warp-cooperative ignore-row subtraction (one warp per row) ----
        for (int i = wrp; i < nign; i += TPB / 32) {
            const int a = siglist[i];
            const float4* row4 = (const float4*)(logits + ((size_t)b * AA + a) * KK);
            float t = (lane < KK / 4) ? focal4(row4[lane]) : 0.0f;
            #pragma unroll
            for (int o = 16; o > 0; o >>= 1)
                t += __shfl_down_sync(0xffffffffu, t, o);
            if (lane == 0) s -= t;
        }
    }

    // ---------- block reduction, one atomic each ----------
    #pragma unroll
    for (int o = 16; o > 0; o >>= 1) {
        s    += __shfl_down_sync(0xffffffffu, s, o);
        rsum += __shfl_down_sync(0xffffffffu, rsum, o);
        myblk_pos += __shfl_down_sync(0xffffffffu, myblk_pos, o);
    }
    __shared__ int psum[8];
    if (lane == 0) { wsum[wrp] = s; wsum2[wrp] = rsum; psum[wrp] = myblk_pos; }
    __syncthreads();

    if (tid == 0) {
        float t = 0.0f, t2 = 0.0f;
        int np = 0;
        #pragma unroll
        for (int i = 0; i < 8; ++i) { t += wsum[i]; t2 += wsum2[i]; np += psum[i]; }
        if (t != 0.0f)  atomicAdd(&g_cls_raw[b], t);
        if (t2 != 0.0f) atomicAdd(&g_reg_raw[b], t2);
        if (np)         atomicAdd(&g_numpos[b], np);
        finalize_if_last(out);
    }
}

extern "C" void kernel_launch(void* const* d_in, const int* in_sizes, int n_in,
                              void* d_out, int out_size) {
    const float* logits  = (const float*)d_in[0];
    const float* regp    = (const float*)d_in[1];
    const float* anchors = (const float*)d_in[2];
    const float* boxes   = (const float*)d_in[3];
    const int*   cls     = (const int*)d_in[4];
    float* out = (float*)d_out;

    dim3 grid(NBLKX, BB);
    retina_hetero_kernel<<<grid, TPB>>>(logits, regp, anchors, boxes, cls, out);
}

// round 17
// speedup vs baseline: 1.0627x; 1.0476x over previous
#include <cuda_runtime.h>
#include <math.h>

#define BB 8
#define AA 49104
#define MM 50
#define KK 80
#define TPB 256
#define NBLKX_SWP 148
#define NBLKX_SCR 96
#define SCR_APB 512                       // anchors per screen block
#define NBLKX (NBLKX_SWP + NBLKX_SCR)     // 244
#define NBLKS (NBLKX * BB)                // 1952
#define N4    (AA * (KK / 4))             // 982080 float4s per image
#define CHUNK 6656                        // float4s per sweep block (148*6656 >= N4)

// zero-initialized at module load; finalizer re-zeros after each consume,
// so every graph replay starts clean.
__device__ float g_cls_raw[BB];
__device__ float g_reg_raw[BB];
__device__ int   g_numpos[BB];
__device__ unsigned int g_done;

__device__ __forceinline__ float smooth_l1(float d) {
    const float BETA = 1.0f / 9.0f;
    float ad = fabsf(d);
    return (ad <= BETA) ? (4.5f * ad * ad) : (ad - 0.5f * BETA);
}

// focal bulk term for one float4 of probabilities: sum p^2 * log2(1-p)
__device__ __forceinline__ float focal4(float4 p4) {
    return p4.x * p4.x * __log2f(1.0f - p4.x)
         + p4.y * p4.y * __log2f(1.0f - p4.y)
         + p4.z * p4.z * __log2f(1.0f - p4.z)
         + p4.w * p4.w * __log2f(1.0f - p4.w);
}

__device__ __forceinline__ void finalize_if_last(float* out) {
    __threadfence();
    unsigned int prev = atomicAdd(&g_done, 1u);
    if (prev == NBLKS - 1) {
        float cm = 0.0f, rm = 0.0f;
        #pragma unroll
        for (int bb = 0; bb < BB; ++bb) {
            float np = fmaxf((float)g_numpos[bb], 1.0f);
            cm += (-0.75f * 0.69314718055994531f) * g_cls_raw[bb] / np;
            rm += g_reg_raw[bb] / (4.0f * np);
            g_cls_raw[bb] = 0.0f;
            g_reg_raw[bb] = 0.0f;
            g_numpos[bb] = 0;
        }
        cm *= (1.0f / (float)BB);
        rm *= (1.0f / (float)BB);
        out[0] = cm;
        out[1] = rm;
        out[2] = cm + rm;
        g_done = 0u;
    }
}

__global__ __launch_bounds__(TPB, 8) void retina_hetero_kernel(
    const float* __restrict__ logits,   // (B,A,K)
    const float* __restrict__ regp,     // (B,A,4)
    const float* __restrict__ anchors,  // (A,4)
    const float* __restrict__ boxes,    // (B,M,4)
    const int*   __restrict__ cls,      // (B,M)
    float* __restrict__ out)
{
    const int b = blockIdx.y;
    const int tid = threadIdx.x;
    const int lane = tid & 31;
    const int wrp = tid >> 5;

    __shared__ float wsum[8], wsum2[8];

    float s = 0.0f;      // classification partial (units of p^2*log2(...))
    float rsum = 0.0f;   // regression partial
    int   myblk_pos = 0;

    if (blockIdx.x < NBLKX_SWP) {
        // ======== SWEEP ROLE: contiguous chunk, 4 load chains (32-reg fit) ========
        const float4* __restrict__ L4 = (const float4*)(logits + (size_t)b * AA * KK);
        const unsigned beg = blockIdx.x * CHUNK;
        const unsigned end = min(beg + CHUNK, (unsigned)N4);

        float s0 = 0.0f, s1 = 0.0f, s2 = 0.0f, s3 = 0.0f;
        unsigned j = beg + tid;
        for (; j + 3u * TPB < end; j += 4u * TPB) {
            // 4 independent LDG.128 (streaming, no L2 retention)
            float4 p0 = __ldcs(&L4[j]);
            float4 p1 = __ldcs(&L4[j + 1u * TPB]);
            float4 p2 = __ldcs(&L4[j + 2u * TPB]);
            float4 p3 = __ldcs(&L4[j + 3u * TPB]);
            s0 += focal4(p0);
            s1 += focal4(p1);
            s2 += focal4(p2);
            s3 += focal4(p3);
        }
        for (; j < end; j += TPB)
            s0 += focal4(__ldcs(&L4[j]));
        s = (s0 + s1) + (s2 + s3);
    } else {
        // ================= SCREEN ROLE: assign + corrections =================
        const int xs = blockIdx.x - NBLKX_SWP;       // 0..95
        const int aStart = xs * SCR_APB;

        __shared__ float4 sbox[MM];
        __shared__ float4 saux[MM];   // (2/7)sb, (1/3)sb, sb, cls-bits
        __shared__ int    siglist[SCR_APB];
        __shared__ int    sigcnt, snv;

        if (tid == 0) { sigcnt = 0; snv = MM; }
        __syncthreads();
        if (tid < MM) {
            float4 bx = ((const float4*)boxes)[b * MM + tid];
            float sb = (bx.z - bx.x) * (bx.w - bx.y);
            sbox[tid] = bx;
            float4 au;
            au.x = sb * (2.0f / 7.0f);   // 0.4/(1+0.4) * sb
            au.y = sb * (1.0f / 3.0f);   // 0.5/(1+0.5) * sb
            au.z = sb;
            au.w = __int_as_float(cls[b * MM + tid]);
            saux[tid] = au;
            if (bx.x == -1.0f) atomicMin(&snv, tid);   // valid-first padding
        }
        __syncthreads();
        const int nv = snv;   // uniform -> no divergence

        int npos = 0;
        #pragma unroll
        for (int pass = 0; pass < SCR_APB / TPB; ++pass) {
            const int a = aStart + tid + pass * TPB;
            if (a >= AA) continue;
            float4 an = ((const float4*)anchors)[a];
            const float ax1 = an.x, ay1 = an.y, ax2 = an.z, ay2 = an.w;
            const float aw = ax2 - ax1, ah = ay2 - ay1;
            const float sa = aw * ah;

            // screen: iou >= t <=> inter >= t/(1+t)*(sa+sb), FFMA-fused
            float m4 = -1e30f, m5 = -1e30f;
            #pragma unroll 5
            for (int j = 0; j < nv; ++j) {
                float4 bx = sbox[j];
                float4 au = saux[j];
                float iw = fmaxf(fminf(ax2, bx.z) - fmaxf(ax1, bx.x), 0.0f);
                float ih = fminf(ay2, bx.w) - fmaxf(ay1, bx.y);
                m4 = fmaxf(m4, __fmaf_rn(iw, ih, -au.x));
                m5 = fmaxf(m5, __fmaf_rn(iw, ih, -au.y));
            }
            const bool pos = (m5 >= sa * (1.0f / 3.0f));   // iou_max >= 0.5
            const bool neg = (m4 <  sa * (2.0f / 7.0f));   // iou_max < 0.4

            if (!pos && !neg) siglist[atomicAdd(&sigcnt, 1)] = a;

            if (pos) {
                npos++;
                // cold path: rare (<0.3% of threads). Spills here are fine.
                float bi = -1.0f, bu = 1.0f;
                int bj = 0;
                for (int j = 0; j < nv; ++j) {
                    float4 bx = sbox[j];
                    float iw = fmaxf(fminf(ax2, bx.z) - fmaxf(ax1, bx.x), 0.0f);
                    float ih = fmaxf(fminf(ay2, bx.w) - fmaxf(ay1, bx.y), 0.0f);
                    float inter = iw * ih;
                    float ua = fmaxf(sa + saux[j].z - inter, 1e-8f);
                    if (inter * bu > bi * ua) { bi = inter; bu = ua; bj = j; }
                }

                // focal correction on the positive class
                int c = __float_as_int(saux[bj].w) - 1;
                float praw = __ldg(logits + ((size_t)b * AA + a) * KK + c);
                float p = fminf(fmaxf(praw, 1e-4f), 1.0f - 1e-4f);
                float q = 1.0f - p;
                s += (1.0f / 3.0f) * q * q * __log2f(p) - p * p * __log2f(q);

                // regression smooth-L1
                float4 gb = sbox[bj];
                float acx = ax1 + 0.5f * aw;
                float acy = ay1 + 0.5f * ah;
                float gw0 = gb.z - gb.x, gh0 = gb.w - gb.y;
                float gcx = gb.x + 0.5f * gw0;
                float gcy = gb.y + 0.5f * gh0;
                float gw = fmaxf(gw0, 1.0f), gh = fmaxf(gh0, 1.0f);
                float4 rp = ((const float4*)regp)[b * AA + a];
                float t0 = ((gcx - acx) / aw) * 10.0f;
                float t1 = ((gcy - acy) / ah) * 10.0f;
                float t2 = logf(gw / aw) * 5.0f;
                float t3 = logf(gh / ah) * 5.0f;
                rsum += smooth_l1(t0 - rp.x) + smooth_l1(t1 - rp.y)
                      + smooth_l1(t2 - rp.z) + smooth_l1(t3 - rp.w);
            }
        }
        myblk_pos = npos;
        __syncthreads();
        const int nign = sigcnt;

        // ---- warp-cooperative ignore-row subtraction (one warp per row) ----
        for (int i = wrp; i < nign; i += TPB / 32) {
            const int a = siglist[i];
            const float4* row4 = (const float4*)(logits + ((size_t)b * AA + a) * KK);
            float t = (lane < KK / 4) ? focal4(row4[lane]) : 0.0f;
            #pragma unroll
            for (int o = 16; o > 0; o >>= 1)
                t += __shfl_down_sync(0xffffffffu, t, o);
            if (lane == 0) s -= t;
        }
    }

    // ---------- block reduction, one atomic each ----------
    #pragma unroll
    for (int o = 16; o > 0; o >>= 1) {
        s    += __shfl_down_sync(0xffffffffu, s, o);
        rsum += __shfl_down_sync(0xffffffffu, rsum, o);
        myblk_pos += __shfl_down_sync(0xffffffffu, myblk_pos, o);
    }
    __shared__ int psum[8];
    if (lane == 0) { wsum[wrp] = s; wsum2[wrp] = rsum; psum[wrp] = myblk_pos; }
    __syncthreads();

    if (tid == 0) {
        float t = 0.0f, t2 = 0.0f;
        int np = 0;
        #pragma unroll
        for (int i = 0; i < 8; ++i) { t += wsum[i]; t2 += wsum2[i]; np += psum[i]; }
        if (t != 0.0f)  atomicAdd(&g_cls_raw[b], t);
        if (t2 != 0.0f) atomicAdd(&g_reg_raw[b], t2);
        if (np)         atomicAdd(&g_numpos[b], np);
        finalize_if_last(out);
    }
}

extern "C" void kernel_launch(void* const* d_in, const int* in_sizes, int n_in,
                              void* d_out, int out_size) {
    const float* logits  = (const float*)d_in[0];
    const float* regp    = (const float*)d_in[1];
    const float* anchors = (const float*)d_in[2];
    const float* boxes   = (const float*)d_in[3];
    const int*   cls     = (const int*)d_in[4];
    float* out = (float*)d_out;

    dim3 grid(NBLKX, BB);
    retina_hetero_kernel<<<grid, TPB>>>(logits, regp, anchors, boxes, cls, out);
}